// round 15
// baseline (speedup 1.0000x reference)
#include <cuda_runtime.h>
#include <cuda_fp16.h>
#include <cstdint>
#include <math.h>

// ---------------------------------------------------------------- constants
#define BB 4
#define TT 4096
#define DD 1024
#define MM (BB * TT)            // 16384
#define TOTL ((size_t)MM * DD)  // 16777216
#define BD (BB * DD)            // 4096
#define CH 256                  // scan chunks per sequence
#define CLEN (TT / CH)          // 16

#define LOG8F 2.0794415416798357f

// ---------------------------------------------------------------- scratch
__device__ __half g_zr[MM * DD];    // fp16 raw zr
__device__ __half g_zi[MM * DD];    // fp16 raw zi
__device__ __half g_zx[MM * DD];    // fp16 raw zx
__device__ __half g_af[MM * DD];    // fp16 decay a (pass1 -> pass3)
__device__ __half g_uf[MM * DD];    // fp16 input term u (pass1 -> pass3)
__device__ __half g_xh[MM * DD];    // fp16 x
__device__ __half g_wh[3][DD * DD]; // fp16 Wr, Wi, Wx
__device__ float  g_P[BD * CH];
__device__ float  g_Q[BD * CH];
__device__ float  g_S[BD * CH];

// ---------------------------------------------------------------- ptx utils
__device__ __forceinline__ uint32_t smem_u32(const void* p) {
    uint32_t a;
    asm("{ .reg .u64 t; cvta.to.shared.u64 t, %1; cvt.u32.u64 %0, t; }" : "=r"(a) : "l"(p));
    return a;
}
__device__ __forceinline__ void mma_f16(float* d, const uint32_t* a, const uint32_t* b) {
    asm volatile(
        "mma.sync.aligned.m16n8k16.row.col.f32.f16.f16.f32 "
        "{%0,%1,%2,%3}, {%4,%5,%6,%7}, {%8,%9}, {%0,%1,%2,%3};"
        : "+f"(d[0]), "+f"(d[1]), "+f"(d[2]), "+f"(d[3])
        : "r"(a[0]), "r"(a[1]), "r"(a[2]), "r"(a[3]), "r"(b[0]), "r"(b[1]));
}
__device__ __forceinline__ void ldsm_x4(uint32_t* r, uint32_t addr) {
    asm volatile("ldmatrix.sync.aligned.m8n8.x4.shared.b16 {%0,%1,%2,%3}, [%4];"
                 : "=r"(r[0]), "=r"(r[1]), "=r"(r[2]), "=r"(r[3]) : "r"(addr));
}
__device__ __forceinline__ void cp16(uint32_t saddr, const void* g) {
    asm volatile("cp.async.cg.shared.global [%0], [%1], 16;" :: "r"(saddr), "l"(g));
}
#define CP_COMMIT() asm volatile("cp.async.commit_group;" ::: "memory")
#define CP_WAIT1()  asm volatile("cp.async.wait_group 1;" ::: "memory")

// streaming (evict-first) memory ops
__device__ __forceinline__ void stcs32(void* p, uint32_t v) {
    asm volatile("st.global.cs.b32 [%0], %1;" :: "l"(p), "r"(v) : "memory");
}
__device__ __forceinline__ uint2 ldcs64(const void* p) {
    uint2 v;
    asm volatile("ld.global.cs.v2.b32 {%0,%1}, [%2];" : "=r"(v.x), "=r"(v.y) : "l"(p));
    return v;
}
__device__ __forceinline__ void stcs128(void* p, float4 v) {
    asm volatile("st.global.cs.v4.f32 [%0], {%1,%2,%3,%4};"
                 :: "l"(p), "f"(v.x), "f"(v.y), "f"(v.z), "f"(v.w) : "memory");
}

__device__ __forceinline__ float tanh_a(float x) {
    float y;
    asm("tanh.approx.f32 %0, %1;" : "=f"(y) : "f"(x));
    return y;
}

// gate math via tanh.approx: sigmoid(x) = 0.5 + 0.5*tanh(x/2)
__device__ __forceinline__ void gate_au(float zrv, float ziv, float zx,
                                        float& a, float& u) {
    const float r = fmaf(tanh_a(0.5f * zrv), 0.5f, 0.5f);
    // a = sigmoid(-log8 * r) = 0.5 - 0.5*tanh(log8*r/2)
    a = fmaf(tanh_a(0.5f * LOG8F * r), -0.5f, 0.5f);
    const float g = sqrtf(fmaxf(1.f - a * a, 1e-6f));
    const float iv = fmaf(tanh_a(0.5f * ziv), 0.5f, 0.5f);
    u = g * iv * zx;
}

// fp32 -> fp16 pre-conversion (4 floats / thread)
__global__ void __launch_bounds__(256)
cvt_half(const float* __restrict__ src, __half* __restrict__ dst) {
    const size_t i = (size_t)blockIdx.x * 256 + threadIdx.x;
    float4 v = ((const float4*)src)[i];
    half2 h01 = __floats2half2_rn(v.x, v.y);
    half2 h23 = __floats2half2_rn(v.z, v.w);
    ((uint2*)dst)[i] = make_uint2(*(uint32_t*)&h01, *(uint32_t*)&h23);
}
__global__ void __launch_bounds__(256)
cvt_w3(const float* __restrict__ wr, const float* __restrict__ wi,
       const float* __restrict__ wx, __half* __restrict__ dst) {
    const int grp = blockIdx.x >> 10;
    const size_t i = ((size_t)(blockIdx.x & 1023)) * 256 + threadIdx.x;
    const float* src = (grp == 0) ? wr : ((grp == 1) ? wi : wx);
    float4 v = ((const float4*)src)[i];
    half2 h01 = __floats2half2_rn(v.x, v.y);
    half2 h23 = __floats2half2_rn(v.z, v.w);
    ((uint2*)(dst + (size_t)grp * DD * DD))[i] = make_uint2(*(uint32_t*)&h01, *(uint32_t*)&h23);
}

// ================================================================ fp16 GEMM
// C[m,n] = sum_k A[m,k]*W[n,k] (NT), fp16 in / fp32 accum / fp16 out.
// 128x128x64 CTA tile, 8 warps (2Mx4N), 64x32 warp tile, 3-stage cp.async.
// grid.z selects weight matrix and destination (zr / zi / zx).
#define BM 128
#define BN 128
#define BK 64
#define NK (DD / BK)                   // 16
#define STG 3
#define RSH 72                         // halves per smem row (64 + 8 pad)
#define HSTAGE (128 * RSH)             // halves per stage (9216)
#define B_OFF (STG * HSTAGE)           // halves
#define SMEM_H (2 * STG * HSTAGE * 2)  // 110592 bytes

__global__ void __launch_bounds__(256, 2)
gemm3(const __half* __restrict__ A, const __half* __restrict__ Wbase)
{
    extern __shared__ __half hsmem[];
    const uint32_t sb = smem_u32(hsmem);
    const int tid = threadIdx.x;
    const int wid = tid >> 5;
    const int lane = tid & 31;
    const int r = lane >> 2;
    const int c = lane & 3;
    const int mw = (wid >> 2) * 64;
    const int nw = (wid & 3) * 32;
    const int bm = blockIdx.y * BM;
    const int bn = blockIdx.x * BN;
    const int z  = blockIdx.z;

    const __half* W = Wbase + (size_t)z * DD * DD;
    __half* Cd = (z == 0) ? g_zr : ((z == 1) ? g_zi : g_zx);

    const int a_row = mw + (lane & 15);
    const int a_k8  = (lane >> 4) * 8;
    const int b_n   = nw + ((lane >> 4) << 3) + (lane & 7);
    const int b_k8  = ((lane >> 3) & 1) * 8;

    float acc[4][4][4];
#pragma unroll
    for (int i = 0; i < 4; i++)
#pragma unroll
        for (int j = 0; j < 4; j++)
#pragma unroll
            for (int q = 0; q < 4; q++) acc[i][j][q] = 0.f;

    auto issue = [&](int kt) {
        const int s = kt % STG;
        const int k0 = kt * BK;
#pragma unroll
        for (int i = 0; i < 4; i++) {
            const int u = tid + 256 * i;
            const int row = u >> 3, c8 = (u & 7) * 8;
            cp16(sb + 2 * (s * HSTAGE + row * RSH + c8),
                 A + (size_t)(bm + row) * DD + k0 + c8);
            cp16(sb + 2 * (B_OFF + s * HSTAGE + row * RSH + c8),
                 W + (size_t)(bn + row) * DD + k0 + c8);
        }
    };

    issue(0); CP_COMMIT();
    issue(1); CP_COMMIT();

    for (int kt = 0; kt < NK; kt++) {
        CP_WAIT1();
        __syncthreads();
        const int s = kt % STG;
        const uint32_t abase = sb + 2 * (s * HSTAGE + a_row * RSH + a_k8);
        const uint32_t bbase = sb + 2 * (B_OFF + s * HSTAGE + b_n * RSH + b_k8);
#pragma unroll
        for (int kk = 0; kk < BK; kk += 16) {
            uint32_t af[4][4], bf[4][2];
#pragma unroll
            for (int mi = 0; mi < 4; mi++)
                ldsm_x4(af[mi], abase + 2 * (mi * 16 * RSH + kk));
#pragma unroll
            for (int nj = 0; nj < 2; nj++) {
                uint32_t t[4];
                ldsm_x4(t, bbase + 2 * (nj * 16 * RSH + kk));
                bf[nj * 2][0] = t[0]; bf[nj * 2][1] = t[1];
                bf[nj * 2 + 1][0] = t[2]; bf[nj * 2 + 1][1] = t[3];
            }
#pragma unroll
            for (int mi = 0; mi < 4; mi++)
#pragma unroll
                for (int ni = 0; ni < 4; ni++)
                    mma_f16(acc[mi][ni], af[mi], bf[ni]);
            if (kk == 0) {   // overlap next-stage issue with remaining MMA
                if (kt + 2 < NK) issue(kt + 2);
                CP_COMMIT();
            }
        }
    }

    // epilogue: stream fp16 raw results (evict-first: keep x/W tiles in L2)
#pragma unroll
    for (int mi = 0; mi < 4; mi++) {
#pragma unroll
        for (int ni = 0; ni < 4; ni++) {
            const int m0 = bm + mw + mi * 16 + r;
            const int n  = bn + nw + ni * 8 + c * 2;
            half2 lo = __floats2half2_rn(acc[mi][ni][0], acc[mi][ni][1]);
            half2 hi = __floats2half2_rn(acc[mi][ni][2], acc[mi][ni][3]);
            stcs32(Cd + (size_t)m0 * DD + n, *(uint32_t*)&lo);
            stcs32(Cd + (size_t)(m0 + 8) * DD + n, *(uint32_t*)&hi);
        }
    }
}

// ---------------------------------------------------------------- scan
// pass1: 4 d's per thread. Read zr/zi/zx (streaming), gate once, store fp16
// (a,u), emit (P, Q) as float4.
__global__ void __launch_bounds__(256)
scan_pass1(const float* __restrict__ br, const float* __restrict__ bi)
{
    const int g = blockIdx.x * 256 + threadIdx.x;   // 0..BB*CH*256-1
    const int d = (g & 255) * 4;
    const int ch = (g >> 8) & (CH - 1);
    const int b = g >> 16;
    const size_t base = ((size_t)b * TT + (size_t)ch * CLEN) * DD + d;
    const float4 br4 = *(const float4*)(br + d);
    const float4 bi4 = *(const float4*)(bi + d);

    float P[4] = {1.f, 1.f, 1.f, 1.f};
    float Q[4] = {0.f, 0.f, 0.f, 0.f};
#pragma unroll
    for (int j = 0; j < CLEN; j++) {
        const size_t idx = base + (size_t)j * DD;
        uint2 vr = ldcs64(g_zr + idx);
        uint2 vi = ldcs64(g_zi + idx);
        uint2 vx = ldcs64(g_zx + idx);
        float2 zr0 = __half22float2(*(half2*)&vr.x), zr1 = __half22float2(*(half2*)&vr.y);
        float2 zi0 = __half22float2(*(half2*)&vi.x), zi1 = __half22float2(*(half2*)&vi.y);
        float2 zx0 = __half22float2(*(half2*)&vx.x), zx1 = __half22float2(*(half2*)&vx.y);
        float a[4], u[4];
        gate_au(zr0.x + br4.x, zi0.x + bi4.x, zx0.x, a[0], u[0]);
        gate_au(zr0.y + br4.y, zi0.y + bi4.y, zx0.y, a[1], u[1]);
        gate_au(zr1.x + br4.z, zi1.x + bi4.z, zx1.x, a[2], u[2]);
        gate_au(zr1.y + br4.w, zi1.y + bi4.w, zx1.y, a[3], u[3]);
        half2 a01 = __floats2half2_rn(a[0], a[1]), a23 = __floats2half2_rn(a[2], a[3]);
        half2 u01 = __floats2half2_rn(u[0], u[1]), u23 = __floats2half2_rn(u[2], u[3]);
        *(uint2*)(g_af + idx) = make_uint2(*(uint32_t*)&a01, *(uint32_t*)&a23);
        *(uint2*)(g_uf + idx) = make_uint2(*(uint32_t*)&u01, *(uint32_t*)&u23);
#pragma unroll
        for (int q = 0; q < 4; q++) {
            P[q] *= a[q];
            Q[q] = fmaf(a[q], Q[q], u[q]);
        }
    }
    const int o = ((b * CH + ch) << 10) | d;
    *(float4*)&g_P[o] = make_float4(P[0], P[1], P[2], P[3]);
    *(float4*)&g_Q[o] = make_float4(Q[0], Q[1], Q[2], Q[3]);
}

// pass2: serial over chunks per (b, d); emits chunk start states + h_last.
__global__ void __launch_bounds__(256)
scan_pass2(const float* __restrict__ h0, float* __restrict__ hlast)
{
    const int bd = blockIdx.x * 256 + threadIdx.x;
    const int b = bd >> 10, d = bd & (DD - 1);
    float S = h0[bd];
#pragma unroll 8
    for (int ch = 0; ch < CH; ch++) {
        const int idx = ((b * CH + ch) << 10) | d;
        g_S[idx] = S;
        S = fmaf(g_P[idx], S, g_Q[idx]);
    }
    hlast[bd] = S;
}

// pass3: 4 d's per thread. Read fp16 (a,u), scan, stream out float4.
__global__ void __launch_bounds__(256)
scan_pass3(float* __restrict__ out)
{
    const int g = blockIdx.x * 256 + threadIdx.x;
    const int d = (g & 255) * 4;
    const int ch = (g >> 8) & (CH - 1);
    const int b = g >> 16;
    const size_t base = ((size_t)b * TT + (size_t)ch * CLEN) * DD + d;

    const int o = ((b * CH + ch) << 10) | d;
    float4 h = *(const float4*)&g_S[o];
#pragma unroll
    for (int j = 0; j < CLEN; j++) {
        const size_t idx = base + (size_t)j * DD;
        uint2 va = *(const uint2*)(g_af + idx);
        uint2 vu = *(const uint2*)(g_uf + idx);
        float2 a0 = __half22float2(*(half2*)&va.x), a1 = __half22float2(*(half2*)&va.y);
        float2 u0 = __half22float2(*(half2*)&vu.x), u1 = __half22float2(*(half2*)&vu.y);
        h.x = fmaf(a0.x, h.x, u0.x);
        h.y = fmaf(a0.y, h.y, u0.y);
        h.z = fmaf(a1.x, h.z, u1.x);
        h.w = fmaf(a1.y, h.w, u1.y);
        stcs128(out + idx, h);
    }
}

// ---------------------------------------------------------------- launch
extern "C" void kernel_launch(void* const* d_in, const int* in_sizes, int n_in,
                              void* d_out, int out_size)
{
    const float* x   = (const float*)d_in[0];
    const float* h0  = (const float*)d_in[1];
    const float* W_r = (const float*)d_in[2];
    const float* b_r = (const float*)d_in[3];
    const float* W_i = (const float*)d_in[4];
    const float* b_i = (const float*)d_in[5];
    const float* W_x = (const float*)d_in[6];
    float* out = (float*)d_out;

    __half *xh, *wh;
    cudaGetSymbolAddress((void**)&xh, g_xh);
    cudaGetSymbolAddress((void**)&wh, g_wh);

    cudaFuncSetAttribute(gemm3, cudaFuncAttributeMaxDynamicSharedMemorySize, SMEM_H);

    cvt_half<<<(int)(TOTL / 4 / 256), 256>>>(x, xh);
    cvt_w3<<<3 * 1024, 256>>>(W_r, W_i, W_x, wh);

    dim3 grid(DD / BN, MM / BM, 3);   // (8, 128, 3): all three GEMMs
    gemm3<<<grid, 256, SMEM_H>>>(xh, wh);

    scan_pass1<<<(BB * CH * 256) / 256, 256>>>(b_r, b_i);
    scan_pass2<<<BD / 256, 256>>>(h0, out + TOTL);
    scan_pass3<<<(BB * CH * 256) / 256, 256>>>(out);
}